// round 7
// baseline (speedup 1.0000x reference)
#include <cuda_runtime.h>
#include <cuda_fp16.h>
#include <math.h>
#include <stdint.h>

// Problem dims
#define BB 64
#define TT 512
#define EE 300
#define KE 320
#define UU 256
#define GG 768
#define CC 20

// ------------------------------------------------------------------
// Scratch
// ------------------------------------------------------------------
__device__ __half g_eh  [BB * TT * KE];
__device__ __half g_h1h [BB * TT * 2 * UU];
__device__ float  g_xwf [BB * TT * GG];
__device__ float  g_xwb [BB * TT * GG];
__device__ float  g_h2  [BB * 2 * UU];
__device__ __half g_rkh1f[UU * GG];
__device__ __half g_rkh1b[UU * GG];
__device__ __half g_rkh2f[UU * GG];
__device__ __half g_rkh2b[UU * GG];
__device__ __half g_w1hf[KE * GG];
__device__ __half g_w1hb[KE * GG];
__device__ __half g_w2hf[2 * UU * GG];
__device__ __half g_w2hb[2 * UU * GG];

// ------------------------------------------------------------------
// 0) all fp32 -> fp16 conversions, one kernel
// ------------------------------------------------------------------
__global__ void convert_all(const float* __restrict__ rk1f, const float* __restrict__ rk1b,
                            const float* __restrict__ rk2f, const float* __restrict__ rk2b,
                            const float* __restrict__ k1f,  const float* __restrict__ k1b,
                            const float* __restrict__ k2f,  const float* __restrict__ k2b,
                            __half* rkh1f, __half* rkh1b, __half* rkh2f, __half* rkh2b,
                            __half* w1hf,  __half* w1hb,  __half* w2hf,  __half* w2hb) {
    int seg = blockIdx.y;
    int i = blockIdx.x * blockDim.x + threadIdx.x;
    const float* src = nullptr; __half* dst = nullptr; int n = 0; bool pad = false;
    switch (seg) {
        case 0: src = rk1f; dst = rkh1f; n = UU * GG; break;
        case 1: src = rk1b; dst = rkh1b; n = UU * GG; break;
        case 2: src = rk2f; dst = rkh2f; n = UU * GG; break;
        case 3: src = rk2b; dst = rkh2b; n = UU * GG; break;
        case 4: src = k1f;  dst = w1hf;  n = KE * GG; pad = true; break;
        case 5: src = k1b;  dst = w1hb;  n = KE * GG; pad = true; break;
        case 6: src = k2f;  dst = w2hf;  n = 2 * UU * GG; break;
        default: src = k2b; dst = w2hb;  n = 2 * UU * GG; break;
    }
    if (i >= n) return;
    if (pad) {
        int r = i / GG;
        dst[i] = (r < EE) ? __float2half_rn(src[i]) : __half(0.f);
    } else {
        dst[i] = __float2half_rn(src[i]);
    }
}

// ------------------------------------------------------------------
// 1) embedding gather -> fp16, padded to 320
// ------------------------------------------------------------------
__global__ void gather_h_kernel(const int* __restrict__ x,
                                const float* __restrict__ emb,
                                __half* __restrict__ eh) {
    int row = blockIdx.x;
    int t = threadIdx.x;
    const float* src = emb + (size_t)x[row] * EE;
    __half2* dst = reinterpret_cast<__half2*>(eh + (size_t)row * KE);
    if (t < EE / 2) {
        float2 v = *reinterpret_cast<const float2*>(src + 2 * t);
        dst[t] = __floats2half2_rn(v.x, v.y);
    } else if (t < KE / 2) {
        dst[t] = __floats2half2_rn(0.f, 0.f);
    }
}

// ------------------------------------------------------------------
// mma/ldmatrix primitives
// ------------------------------------------------------------------
__device__ __forceinline__ void ldsm_x4(uint32_t& r0, uint32_t& r1, uint32_t& r2, uint32_t& r3,
                                        uint32_t addr) {
    asm volatile("ldmatrix.sync.aligned.m8n8.x4.shared.b16 {%0,%1,%2,%3}, [%4];"
                 : "=r"(r0), "=r"(r1), "=r"(r2), "=r"(r3) : "r"(addr));
}
__device__ __forceinline__ void ldsm_x4_t(uint32_t& r0, uint32_t& r1, uint32_t& r2, uint32_t& r3,
                                          uint32_t addr) {
    asm volatile("ldmatrix.sync.aligned.m8n8.x4.trans.shared.b16 {%0,%1,%2,%3}, [%4];"
                 : "=r"(r0), "=r"(r1), "=r"(r2), "=r"(r3) : "r"(addr));
}
__device__ __forceinline__ void ldsm_x2(uint32_t& r0, uint32_t& r1, uint32_t addr) {
    asm volatile("ldmatrix.sync.aligned.m8n8.x2.shared.b16 {%0,%1}, [%2];"
                 : "=r"(r0), "=r"(r1) : "r"(addr));
}
__device__ __forceinline__ void mma16816(float* c, const uint32_t* a, const uint32_t* b) {
    asm volatile("mma.sync.aligned.m16n8k16.row.col.f32.f16.f16.f32 "
                 "{%0,%1,%2,%3}, {%4,%5,%6,%7}, {%8,%9}, {%0,%1,%2,%3};"
                 : "+f"(c[0]), "+f"(c[1]), "+f"(c[2]), "+f"(c[3])
                 : "r"(a[0]), "r"(a[1]), "r"(a[2]), "r"(a[3]), "r"(b[0]), "r"(b[1]));
}

#define CPA16(s, g) asm volatile("cp.async.cg.shared.global [%0], [%1], 16;" :: "r"(s), "l"(g))
#define CPA_COMMIT() asm volatile("cp.async.commit_group;" ::: "memory")
#define CPA_WAIT2()  asm volatile("cp.async.wait_group 2;" ::: "memory")

// ------------------------------------------------------------------
// 2) Fused dual HGEMM (fwd+bwd), 3-stage cp.async pipeline
// ------------------------------------------------------------------
#define SA2 40
#define SB 136
#define ASB (128 * SA2 * 2)
#define BSB (32 * SB * 2)

__global__ __launch_bounds__(256)
void hgemm_dual(const __half* __restrict__ A,
                const __half* __restrict__ Bf, const __half* __restrict__ Bb,
                const float* __restrict__ biasf, const float* __restrict__ biasb,
                float* __restrict__ Cf, float* __restrict__ Cb,
                int K, int lda) {
    __shared__ __half As[3][128 * SA2];
    __shared__ __half Bs[3][32 * SB];

    int tid  = threadIdx.x;
    int w    = tid >> 5;
    int lane = tid & 31;
    int half_sel = blockIdx.x / 6;
    const __half* Bw  = half_sel ? Bb : Bf;
    const float* bias = half_sel ? biasb : biasf;
    float* C          = half_sel ? Cb : Cf;
    int bm = blockIdx.y * 128;
    int bn = (blockIdx.x % 6) * 128;
    int wm = (w >> 2) * 64;
    int wn = (w & 3) * 32;

    float acc[4][4][4];
#pragma unroll
    for (int mi = 0; mi < 4; mi++)
#pragma unroll
        for (int ni = 0; ni < 4; ni++)
#pragma unroll
            for (int c = 0; c < 4; c++) acc[mi][ni][c] = 0.f;

    int arow = tid >> 1, acol = (tid & 1) * 16;
    int brow = tid >> 3, bcol = (tid & 7) * 16;
    const __half* Ag = A + (size_t)(bm + arow) * lda + acol;
    const __half* Bg = Bw + (size_t)brow * GG + bn + bcol;

    uint32_t as_st = (uint32_t)__cvta_generic_to_shared(&As[0][arow * SA2 + acol]);
    uint32_t bs_st = (uint32_t)__cvta_generic_to_shared(&Bs[0][brow * SB + bcol]);

    uint32_t a_addr[4], b_addr[2];
#pragma unroll
    for (int mi = 0; mi < 4; mi++) {
        int m  = wm + mi * 16 + (lane & 15);
        int kc = (lane >> 4) * 8;
        a_addr[mi] = (uint32_t)__cvta_generic_to_shared(&As[0][m * SA2 + kc]);
    }
#pragma unroll
    for (int nj = 0; nj < 2; nj++) {
        int kr = lane & 15;
        int nc = wn + nj * 16 + (lane >> 4) * 8;
        b_addr[nj] = (uint32_t)__cvta_generic_to_shared(&Bs[0][kr * SB + nc]);
    }

    int KT = K >> 5;

    // prologue: stages 0,1
#pragma unroll
    for (int st = 0; st < 2; st++) {
        const __half* Agp = Ag + st * 32;
        const __half* Bgp = Bg + (size_t)st * 32 * GG;
        CPA16(as_st + st * ASB, Agp);
        CPA16(as_st + st * ASB + 16, Agp + 8);
        CPA16(bs_st + st * BSB, Bgp);
        CPA16(bs_st + st * BSB + 16, Bgp + 8);
        CPA_COMMIT();
    }

    for (int kt = 0; kt < KT; kt++) {
        int cur = kt % 3;
        if (kt + 2 < KT) {
            int nb = (kt + 2) % 3;
            const __half* Agn = Ag + (kt + 2) * 32;
            const __half* Bgn = Bg + (size_t)(kt + 2) * 32 * GG;
            CPA16(as_st + nb * ASB, Agn);
            CPA16(as_st + nb * ASB + 16, Agn + 8);
            CPA16(bs_st + nb * BSB, Bgn);
            CPA16(bs_st + nb * BSB + 16, Bgn + 8);
        }
        CPA_COMMIT();
        CPA_WAIT2();
        __syncthreads();

        uint32_t aoff = cur * ASB;
        uint32_t boff = cur * BSB;
#pragma unroll
        for (int kk = 0; kk < 2; kk++) {
            uint32_t afr[4][4];
            uint32_t bfr[4][2];
#pragma unroll
            for (int mi = 0; mi < 4; mi++)
                ldsm_x4(afr[mi][0], afr[mi][1], afr[mi][2], afr[mi][3],
                        a_addr[mi] + aoff + kk * 16 * 2);
#pragma unroll
            for (int nj = 0; nj < 2; nj++) {
                uint32_t r0, r1, r2, r3;
                ldsm_x4_t(r0, r1, r2, r3, b_addr[nj] + boff + kk * 16 * SB * 2);
                bfr[2 * nj][0] = r0; bfr[2 * nj][1] = r1;
                bfr[2 * nj + 1][0] = r2; bfr[2 * nj + 1][1] = r3;
            }
#pragma unroll
            for (int mi = 0; mi < 4; mi++)
#pragma unroll
                for (int ni = 0; ni < 4; ni++)
                    mma16816(acc[mi][ni], afr[mi], bfr[ni]);
        }
        __syncthreads();
    }

#pragma unroll
    for (int mi = 0; mi < 4; mi++) {
#pragma unroll
        for (int ni = 0; ni < 4; ni++) {
            int r0 = bm + wm + mi * 16 + (lane >> 2);
            int c0 = bn + wn + ni * 8 + (lane & 3) * 2;
            float bv0 = bias[c0], bv1 = bias[c0 + 1];
            float* p0 = C + (size_t)r0 * GG + c0;
            float* p1 = C + (size_t)(r0 + 8) * GG + c0;
            p0[0] = acc[mi][ni][0] + bv0;
            p0[1] = acc[mi][ni][1] + bv1;
            p1[0] = acc[mi][ni][2] + bv0;
            p1[1] = acc[mi][ni][3] + bv1;
        }
    }
}

// ------------------------------------------------------------------
// 3) GRU recurrence: cluster(8), reg-resident weight frags, 4 acc chains,
//    tanh.approx gates, mbarrier phase sync (no cluster.sync in loop).
// ------------------------------------------------------------------
#define CLS 8
#define W_STRIDE 104
#define H_STRIDE 264
#define GT_STRIDE 100
#define OFF_W 0
#define OFF_H (256 * W_STRIDE * 2)
#define OFF_G (OFF_H + 2 * 16 * H_STRIDE * 2)
#define OFF_MB (OFF_G + 8 * GT_STRIDE * 4)
#define GRU_SMEM2 (OFF_MB + 16)
#define MB_COUNT 512   // 64 writers/CTA * 8 CTAs

__device__ __forceinline__ void cluster_arrive_() {
    asm volatile("barrier.cluster.arrive.aligned;" ::: "memory");
}
__device__ __forceinline__ void cluster_wait_() {
    asm volatile("barrier.cluster.wait.aligned;" ::: "memory");
}
__device__ __forceinline__ float tanh_fast(float x) {
    float y;
    asm("tanh.approx.f32 %0, %1;" : "=f"(y) : "f"(x));
    return y;
}
__device__ __forceinline__ float sig_fast(float x) {
    return fmaf(0.5f, tanh_fast(0.5f * x), 0.5f);
}
__device__ __forceinline__ void mbar_wait(uint32_t mb, uint32_t parity) {
    asm volatile(
        "{\n\t.reg .pred p;\n\t"
        "WL%=:\n\t"
        "mbarrier.try_wait.parity.acquire.cluster.shared::cta.b64 p, [%0], %1, 0x989680;\n\t"
        "@p bra WD%=;\n\t"
        "bra WL%=;\n\t"
        "WD%=:\n\t}"
        :: "r"(mb), "r"(parity) : "memory");
}
__device__ __forceinline__ void st_cluster_u64(uint32_t laddr, uint32_t rnk, unsigned long long v) {
    uint32_t ra;
    asm volatile("mapa.shared::cluster.u32 %0, %1, %2;" : "=r"(ra) : "r"(laddr), "r"(rnk));
    asm volatile("st.shared::cluster.u64 [%0], %1;" :: "r"(ra), "l"(v) : "memory");
}
__device__ __forceinline__ void mbar_arrive_remote(uint32_t local_mb, uint32_t rnk) {
    uint32_t ra;
    asm volatile("mapa.shared::cluster.u32 %0, %1, %2;" : "=r"(ra) : "r"(local_mb), "r"(rnk));
    asm volatile("mbarrier.arrive.release.cluster.shared::cluster.b64 _, [%0];" :: "r"(ra) : "memory");
}

__global__ __launch_bounds__(256) __cluster_dims__(CLS, 1, 1)
void gru_cluster(const float* __restrict__ xw_f, const float* __restrict__ xw_b,
                 const __half* __restrict__ rkh_f, const __half* __restrict__ rkh_b,
                 const float* __restrict__ bin_f, const float* __restrict__ bin_b,
                 __half* __restrict__ out_seq,
                 float* __restrict__ out_final)
{
    extern __shared__ char sm[];
    __half* wsm  = reinterpret_cast<__half*>(sm + OFF_W);
    __half* hbuf = reinterpret_cast<__half*>(sm + OFF_H);
    float*  gt   = reinterpret_cast<float*>(sm + OFF_G);
    uint32_t smb = (uint32_t)__cvta_generic_to_shared(sm);
    uint32_t mb0 = smb + OFF_MB;
    uint32_t mb1 = smb + OFF_MB + 8;

    int tid = threadIdx.x;
    int lane = tid & 31;
    int wp = tid >> 5;
    uint32_t rank;
    asm("mov.u32 %0, %%cluster_ctarank;" : "=r"(rank));
    int cl  = blockIdx.x / CLS;
    int dir = cl >> 3;
    int bg  = cl & 7;

    const float*  xw  = dir ? xw_b  : xw_f;
    const __half* rkh = dir ? rkh_b : rkh_f;
    const float*  bin = dir ? bin_b : bin_f;

    // init: weights to smem, zero h buffers, init mbarriers
    for (int i = tid; i < 256 * 96; i += 256) {
        int k = i / 96, j = i % 96;
        int gcol = (j >> 5) * 256 + (rank << 5) + (j & 31);
        wsm[k * W_STRIDE + j] = rkh[(size_t)k * GG + gcol];
    }
    for (int i = tid; i < 2 * 16 * H_STRIDE; i += 256) hbuf[i] = __half(0.f);
    if (tid == 0) {
        asm volatile("mbarrier.init.shared.b64 [%0], %1;" :: "r"(mb0), "r"(MB_COUNT) : "memory");
        asm volatile("mbarrier.init.shared.b64 [%0], %1;" :: "r"(mb1), "r"(MB_COUNT) : "memory");
        // complete phase 0 of mb0: buffer 0 (zeros) is ready
        asm volatile("mbarrier.arrive.shared::cta.b64 _, [%0], %1;" :: "r"(mb0), "r"(MB_COUNT) : "memory");
    }

    const int ug = (rank << 5) + lane;
    const float bz = bin[ug];
    const float br = bin[UU + ug];
    const float bh = bin[2 * UU + ug];
    const int gbatch = bg * 8 + wp;

    uint32_t a_off = (uint32_t)((((lane & 7) * H_STRIDE) + ((lane >> 3) & 1) * 8) * 2);
    uint32_t b_addr = smb + OFF_W +
                      (uint32_t)(((lane & 15) * W_STRIDE + 16 * wp + (lane >> 4) * 8) * 2);

    __syncthreads();

    // hoist weight fragments to registers
    uint32_t bReg[16][4];
    if (wp < 6) {
#pragma unroll
        for (int kq = 0; kq < 16; kq++)
            ldsm_x4_t(bReg[kq][0], bReg[kq][1], bReg[kq][2], bReg[kq][3],
                      b_addr + kq * 16 * W_STRIDE * 2);
    }

    cluster_arrive_();
    cluster_wait_();   // mbarrier inits + zeroed buffers visible cluster-wide

    float hn_reg = 0.f;
    float xz, xr, xh;
    {
        int t0 = dir ? (TT - 1) : 0;
        size_t xrow = ((size_t)gbatch * TT + t0) * GG;
        xz = __ldg(&xw[xrow + ug]);
        xr = __ldg(&xw[xrow + UU + ug]);
        xh = __ldg(&xw[xrow + 2 * UU + ug]);
    }

    for (int s = 0; s < TT; s++) {
        int t = dir ? (TT - 1 - s) : s;
        int p = s & 1;

        // wait: buffer p filled (phase parity = (s>>1)&1)
        mbar_wait(p ? mb1 : mb0, (uint32_t)((s >> 1) & 1));

        if (wp < 6) {
            float ac[4][2][4];
#pragma unroll
            for (int c0 = 0; c0 < 4; c0++)
#pragma unroll
                for (int h0 = 0; h0 < 2; h0++)
#pragma unroll
                    for (int e = 0; e < 4; e++) ac[c0][h0][e] = 0.f;
            uint32_t abase = smb + OFF_H + (uint32_t)(p * 16 * H_STRIDE * 2) + a_off;
#pragma unroll
            for (int kq = 0; kq < 16; kq++) {
                uint32_t a[4];
                a[1] = 0u; a[3] = 0u;
                ldsm_x2(a[0], a[2], abase + kq * 32);
                int ch = kq & 3;
                mma16816(ac[ch][0], a, &bReg[kq][0]);
                mma16816(ac[ch][1], a, &bReg[kq][2]);
            }
            int row = lane >> 2;
            int c0  = 16 * wp + (lane & 3) * 2;
#pragma unroll
            for (int h0 = 0; h0 < 2; h0++) {
                float v0 = (ac[0][h0][0] + ac[1][h0][0]) + (ac[2][h0][0] + ac[3][h0][0]);
                float v1 = (ac[0][h0][1] + ac[1][h0][1]) + (ac[2][h0][1] + ac[3][h0][1]);
                *reinterpret_cast<float2*>(&gt[row * GT_STRIDE + c0 + h0 * 8]) = make_float2(v0, v1);
            }
        }

        // prefetch next xw
        float xzn = 0.f, xrn = 0.f, xhn = 0.f;
        if (s + 1 < TT) {
            int tn = dir ? (TT - 2 - s) : (s + 1);
            size_t xrow = ((size_t)gbatch * TT + tn) * GG;
            xzn = __ldg(&xw[xrow + ug]);
            xrn = __ldg(&xw[xrow + UU + ug]);
            xhn = __ldg(&xw[xrow + 2 * UU + ug]);
        }
        __syncthreads();

        // gates
        float rz = gt[wp * GT_STRIDE + lane] + bz;
        float rr = gt[wp * GT_STRIDE + 32 + lane] + br;
        float rh = gt[wp * GT_STRIDE + 64 + lane] + bh;
        float z  = sig_fast(xz + rz);
        float r  = sig_fast(xr + rr);
        float hh = tanh_fast(xh + r * rh);
        float hn = z * hn_reg + (1.f - z) * hh;
        hn_reg = hn;

        // broadcast: writers lane%4==0 pack 4 halves -> u64, store+arrive x8
        float v1f = __shfl_down_sync(0xffffffffu, hn, 1);
        float v2f = __shfl_down_sync(0xffffffffu, hn, 2);
        float v3f = __shfl_down_sync(0xffffffffu, hn, 3);
        if ((lane & 3) == 0) {
            __half2 lo = __halves2half2(__float2half_rn(hn),  __float2half_rn(v1f));
            __half2 hi = __halves2half2(__float2half_rn(v2f), __float2half_rn(v3f));
            unsigned long long pk;
            asm("mov.b64 %0, {%1, %2};" : "=l"(pk)
                : "r"(*reinterpret_cast<uint32_t*>(&lo)), "r"(*reinterpret_cast<uint32_t*>(&hi)));
            uint32_t hoff = smb + OFF_H +
                            (uint32_t)((((p ^ 1) * 16 + wp) * H_STRIDE + ug) * 2);
            uint32_t mtarget = (p ^ 1) ? mb1 : mb0;
#pragma unroll
            for (uint32_t r2 = 0; r2 < CLS; r2++) {
                st_cluster_u64(hoff, r2, pk);
                mbar_arrive_remote(mtarget, r2);
            }
        }

        if (out_seq)
            out_seq[((size_t)gbatch * TT + t) * (2 * UU) + dir * UU + ug] = __float2half_rn(hn);
        xz = xzn; xr = xrn; xh = xhn;
    }

    if (out_final)
        out_final[(size_t)gbatch * (2 * UU) + dir * UU + ug] = hn_reg;

    // no CTA may exit while peers might still store into its SMEM
    cluster_arrive_();
    cluster_wait_();
}

// ------------------------------------------------------------------
// 4) output head
// ------------------------------------------------------------------
__global__ void out_kernel(const float* __restrict__ h2,
                           const float* __restrict__ wout,
                           const float* __restrict__ bout,
                           float* __restrict__ out) {
    int b = blockIdx.x;
    int c = threadIdx.x;
    __shared__ float logits[CC];
    if (c < CC) {
        float acc = bout[c];
        const float* hrow = h2 + (size_t)b * (2 * UU);
#pragma unroll 4
        for (int j = 0; j < 2 * UU; j++) acc += hrow[j] * wout[(size_t)j * CC + c];
        logits[c] = acc;
    }
    __syncthreads();
    if (c == 0) {
        float m = logits[0];
#pragma unroll
        for (int i = 1; i < CC; i++) m = fmaxf(m, logits[i]);
        float s = 0.f;
#pragma unroll
        for (int i = 0; i < CC; i++) { float ev = expf(logits[i] - m); logits[i] = ev; s += ev; }
        float inv = 1.f / s;
#pragma unroll
        for (int i = 0; i < CC; i++) out[(size_t)b * CC + i] = logits[i] * inv;
    }
}

// ------------------------------------------------------------------
// Launcher
// ------------------------------------------------------------------
extern "C" void kernel_launch(void* const* d_in, const int* in_sizes, int n_in,
                              void* d_out, int out_size) {
    const int*   x    = (const int*)  d_in[0];
    const float* emb  = (const float*)d_in[1];
    const float* k1f  = (const float*)d_in[2];
    const float* rk1f = (const float*)d_in[3];
    const float* b1f  = (const float*)d_in[4];
    const float* k1b  = (const float*)d_in[5];
    const float* rk1b = (const float*)d_in[6];
    const float* b1b  = (const float*)d_in[7];
    const float* k2f  = (const float*)d_in[8];
    const float* rk2f = (const float*)d_in[9];
    const float* b2f  = (const float*)d_in[10];
    const float* k2b  = (const float*)d_in[11];
    const float* rk2b = (const float*)d_in[12];
    const float* b2b  = (const float*)d_in[13];
    const float* wout = (const float*)d_in[14];
    const float* bout = (const float*)d_in[15];
    float* out = (float*)d_out;

    __half *eh_p, *h1h_p, *rkh1f_p, *rkh1b_p, *rkh2f_p, *rkh2b_p;
    __half *w1hf_p, *w1hb_p, *w2hf_p, *w2hb_p;
    float *xwf_p, *xwb_p, *h2_p;
    cudaGetSymbolAddress((void**)&eh_p,    g_eh);
    cudaGetSymbolAddress((void**)&h1h_p,   g_h1h);
    cudaGetSymbolAddress((void**)&xwf_p,   g_xwf);
    cudaGetSymbolAddress((void**)&xwb_p,   g_xwb);
    cudaGetSymbolAddress((void**)&h2_p,    g_h2);
    cudaGetSymbolAddress((void**)&rkh1f_p, g_rkh1f);
    cudaGetSymbolAddress((void**)&rkh1b_p, g_rkh1b);
    cudaGetSymbolAddress((void**)&rkh2f_p, g_rkh2f);
    cudaGetSymbolAddress((void**)&rkh2b_p, g_rkh2b);
    cudaGetSymbolAddress((void**)&w1hf_p,  g_w1hf);
    cudaGetSymbolAddress((void**)&w1hb_p,  g_w1hb);
    cudaGetSymbolAddress((void**)&w2hf_p,  g_w2hf);
    cudaGetSymbolAddress((void**)&w2hb_p,  g_w2hb);

    cudaFuncSetAttribute(gru_cluster,
                         cudaFuncAttributeMaxDynamicSharedMemorySize, GRU_SMEM2);

    const int M = BB * TT;
    dim3 hgrid(12, M / 128);   // fused fwd+bwd

    convert_all<<<dim3(384, 8), 1024>>>(rk1f, rk1b, rk2f, rk2b, k1f, k1b, k2f, k2b,
                                        rkh1f_p, rkh1b_p, rkh2f_p, rkh2b_p,
                                        w1hf_p, w1hb_p, w2hf_p, w2hb_p);

    gather_h_kernel<<<M, 160>>>(x, emb, eh_p);

    hgemm_dual<<<hgrid, 256>>>(eh_p, w1hf_p, w1hb_p, b1f, b1b, xwf_p, xwb_p, KE, KE);

    gru_cluster<<<128, 256, GRU_SMEM2>>>(xwf_p, xwb_p, rkh1f_p, rkh1b_p,
                                         b1f + GG, b1b + GG, h1h_p, nullptr);

    hgemm_dual<<<hgrid, 256>>>(h1h_p, w2hf_p, w2hb_p, b2f, b2b, xwf_p, xwb_p,
                               2 * UU, 2 * UU);

    gru_cluster<<<128, 256, GRU_SMEM2>>>(xwf_p, xwb_p, rkh2f_p, rkh2b_p,
                                         b2f + GG, b2b + GG, nullptr, h2_p);

    out_kernel<<<BB, 32>>>(h2_p, wout, bout, out);
}

// round 8
// speedup vs baseline: 2.1076x; 2.1076x over previous
#include <cuda_runtime.h>
#include <cuda_fp16.h>
#include <math.h>
#include <stdint.h>

// Problem dims
#define BB 64
#define TT 512
#define EE 300
#define KE 320
#define UU 256
#define GG 768
#define CC 20

// ------------------------------------------------------------------
// Scratch
// ------------------------------------------------------------------
__device__ __half g_eh  [BB * TT * KE];
__device__ __half g_h1h [BB * TT * 2 * UU];
__device__ float  g_xwf [BB * TT * GG];
__device__ float  g_xwb [BB * TT * GG];
__device__ float  g_h2  [BB * 2 * UU];
__device__ __half g_rkh1f[UU * GG];
__device__ __half g_rkh1b[UU * GG];
__device__ __half g_rkh2f[UU * GG];
__device__ __half g_rkh2b[UU * GG];
__device__ __half g_w1hf[KE * GG];
__device__ __half g_w1hb[KE * GG];
__device__ __half g_w2hf[2 * UU * GG];
__device__ __half g_w2hb[2 * UU * GG];

// ------------------------------------------------------------------
// 0) all fp32 -> fp16 conversions, one kernel
// ------------------------------------------------------------------
__global__ void convert_all(const float* __restrict__ rk1f, const float* __restrict__ rk1b,
                            const float* __restrict__ rk2f, const float* __restrict__ rk2b,
                            const float* __restrict__ k1f,  const float* __restrict__ k1b,
                            const float* __restrict__ k2f,  const float* __restrict__ k2b,
                            __half* rkh1f, __half* rkh1b, __half* rkh2f, __half* rkh2b,
                            __half* w1hf,  __half* w1hb,  __half* w2hf,  __half* w2hb) {
    int seg = blockIdx.y;
    int i = blockIdx.x * blockDim.x + threadIdx.x;
    const float* src = nullptr; __half* dst = nullptr; int n = 0; bool pad = false;
    switch (seg) {
        case 0: src = rk1f; dst = rkh1f; n = UU * GG; break;
        case 1: src = rk1b; dst = rkh1b; n = UU * GG; break;
        case 2: src = rk2f; dst = rkh2f; n = UU * GG; break;
        case 3: src = rk2b; dst = rkh2b; n = UU * GG; break;
        case 4: src = k1f;  dst = w1hf;  n = KE * GG; pad = true; break;
        case 5: src = k1b;  dst = w1hb;  n = KE * GG; pad = true; break;
        case 6: src = k2f;  dst = w2hf;  n = 2 * UU * GG; break;
        default: src = k2b; dst = w2hb;  n = 2 * UU * GG; break;
    }
    if (i >= n) return;
    if (pad) {
        int r = i / GG;
        dst[i] = (r < EE) ? __float2half_rn(src[i]) : __half(0.f);
    } else {
        dst[i] = __float2half_rn(src[i]);
    }
}

// ------------------------------------------------------------------
// 1) embedding gather -> fp16, padded to 320
// ------------------------------------------------------------------
__global__ void gather_h_kernel(const int* __restrict__ x,
                                const float* __restrict__ emb,
                                __half* __restrict__ eh) {
    int row = blockIdx.x;
    int t = threadIdx.x;
    const float* src = emb + (size_t)x[row] * EE;
    __half2* dst = reinterpret_cast<__half2*>(eh + (size_t)row * KE);
    if (t < EE / 2) {
        float2 v = *reinterpret_cast<const float2*>(src + 2 * t);
        dst[t] = __floats2half2_rn(v.x, v.y);
    } else if (t < KE / 2) {
        dst[t] = __floats2half2_rn(0.f, 0.f);
    }
}

// ------------------------------------------------------------------
// mma/ldmatrix primitives
// ------------------------------------------------------------------
__device__ __forceinline__ void ldsm_x4(uint32_t& r0, uint32_t& r1, uint32_t& r2, uint32_t& r3,
                                        uint32_t addr) {
    asm volatile("ldmatrix.sync.aligned.m8n8.x4.shared.b16 {%0,%1,%2,%3}, [%4];"
                 : "=r"(r0), "=r"(r1), "=r"(r2), "=r"(r3) : "r"(addr));
}
__device__ __forceinline__ void ldsm_x4_t(uint32_t& r0, uint32_t& r1, uint32_t& r2, uint32_t& r3,
                                          uint32_t addr) {
    asm volatile("ldmatrix.sync.aligned.m8n8.x4.trans.shared.b16 {%0,%1,%2,%3}, [%4];"
                 : "=r"(r0), "=r"(r1), "=r"(r2), "=r"(r3) : "r"(addr));
}
__device__ __forceinline__ void ldsm_x2(uint32_t& r0, uint32_t& r1, uint32_t addr) {
    asm volatile("ldmatrix.sync.aligned.m8n8.x2.shared.b16 {%0,%1}, [%2];"
                 : "=r"(r0), "=r"(r1) : "r"(addr));
}
__device__ __forceinline__ void mma16816(float* c, const uint32_t* a, const uint32_t* b) {
    asm volatile("mma.sync.aligned.m16n8k16.row.col.f32.f16.f16.f32 "
                 "{%0,%1,%2,%3}, {%4,%5,%6,%7}, {%8,%9}, {%0,%1,%2,%3};"
                 : "+f"(c[0]), "+f"(c[1]), "+f"(c[2]), "+f"(c[3])
                 : "r"(a[0]), "r"(a[1]), "r"(a[2]), "r"(a[3]), "r"(b[0]), "r"(b[1]));
}

#define CPA16(s, g) asm volatile("cp.async.cg.shared.global [%0], [%1], 16;" :: "r"(s), "l"(g))
#define CPA_COMMIT() asm volatile("cp.async.commit_group;" ::: "memory")
#define CPA_WAIT2()  asm volatile("cp.async.wait_group 2;" ::: "memory")

// ------------------------------------------------------------------
// 2) Fused dual HGEMM (fwd+bwd), 3-stage cp.async pipeline
// ------------------------------------------------------------------
#define SA2 40
#define SB 136
#define ASB (128 * SA2 * 2)
#define BSB (32 * SB * 2)

__global__ __launch_bounds__(256)
void hgemm_dual(const __half* __restrict__ A,
                const __half* __restrict__ Bf, const __half* __restrict__ Bb,
                const float* __restrict__ biasf, const float* __restrict__ biasb,
                float* __restrict__ Cf, float* __restrict__ Cb,
                int K, int lda) {
    __shared__ __half As[3][128 * SA2];
    __shared__ __half Bs[3][32 * SB];

    int tid  = threadIdx.x;
    int w    = tid >> 5;
    int lane = tid & 31;
    int half_sel = blockIdx.x / 6;
    const __half* Bw  = half_sel ? Bb : Bf;
    const float* bias = half_sel ? biasb : biasf;
    float* C          = half_sel ? Cb : Cf;
    int bm = blockIdx.y * 128;
    int bn = (blockIdx.x % 6) * 128;
    int wm = (w >> 2) * 64;
    int wn = (w & 3) * 32;

    float acc[4][4][4];
#pragma unroll
    for (int mi = 0; mi < 4; mi++)
#pragma unroll
        for (int ni = 0; ni < 4; ni++)
#pragma unroll
            for (int c = 0; c < 4; c++) acc[mi][ni][c] = 0.f;

    int arow = tid >> 1, acol = (tid & 1) * 16;
    int brow = tid >> 3, bcol = (tid & 7) * 16;
    const __half* Ag = A + (size_t)(bm + arow) * lda + acol;
    const __half* Bg = Bw + (size_t)brow * GG + bn + bcol;

    uint32_t as_st = (uint32_t)__cvta_generic_to_shared(&As[0][arow * SA2 + acol]);
    uint32_t bs_st = (uint32_t)__cvta_generic_to_shared(&Bs[0][brow * SB + bcol]);

    uint32_t a_addr[4], b_addr[2];
#pragma unroll
    for (int mi = 0; mi < 4; mi++) {
        int m  = wm + mi * 16 + (lane & 15);
        int kc = (lane >> 4) * 8;
        a_addr[mi] = (uint32_t)__cvta_generic_to_shared(&As[0][m * SA2 + kc]);
    }
#pragma unroll
    for (int nj = 0; nj < 2; nj++) {
        int kr = lane & 15;
        int nc = wn + nj * 16 + (lane >> 4) * 8;
        b_addr[nj] = (uint32_t)__cvta_generic_to_shared(&Bs[0][kr * SB + nc]);
    }

    int KT = K >> 5;

    // prologue: stages 0,1
#pragma unroll
    for (int st = 0; st < 2; st++) {
        const __half* Agp = Ag + st * 32;
        const __half* Bgp = Bg + (size_t)st * 32 * GG;
        CPA16(as_st + st * ASB, Agp);
        CPA16(as_st + st * ASB + 16, Agp + 8);
        CPA16(bs_st + st * BSB, Bgp);
        CPA16(bs_st + st * BSB + 16, Bgp + 8);
        CPA_COMMIT();
    }

    for (int kt = 0; kt < KT; kt++) {
        int cur = kt % 3;
        if (kt + 2 < KT) {
            int nb = (kt + 2) % 3;
            const __half* Agn = Ag + (kt + 2) * 32;
            const __half* Bgn = Bg + (size_t)(kt + 2) * 32 * GG;
            CPA16(as_st + nb * ASB, Agn);
            CPA16(as_st + nb * ASB + 16, Agn + 8);
            CPA16(bs_st + nb * BSB, Bgn);
            CPA16(bs_st + nb * BSB + 16, Bgn + 8);
        }
        CPA_COMMIT();
        CPA_WAIT2();
        __syncthreads();

        uint32_t aoff = cur * ASB;
        uint32_t boff = cur * BSB;
#pragma unroll
        for (int kk = 0; kk < 2; kk++) {
            uint32_t afr[4][4];
            uint32_t bfr[4][2];
#pragma unroll
            for (int mi = 0; mi < 4; mi++)
                ldsm_x4(afr[mi][0], afr[mi][1], afr[mi][2], afr[mi][3],
                        a_addr[mi] + aoff + kk * 16 * 2);
#pragma unroll
            for (int nj = 0; nj < 2; nj++) {
                uint32_t r0, r1, r2, r3;
                ldsm_x4_t(r0, r1, r2, r3, b_addr[nj] + boff + kk * 16 * SB * 2);
                bfr[2 * nj][0] = r0; bfr[2 * nj][1] = r1;
                bfr[2 * nj + 1][0] = r2; bfr[2 * nj + 1][1] = r3;
            }
#pragma unroll
            for (int mi = 0; mi < 4; mi++)
#pragma unroll
                for (int ni = 0; ni < 4; ni++)
                    mma16816(acc[mi][ni], afr[mi], bfr[ni]);
        }
        __syncthreads();
    }

#pragma unroll
    for (int mi = 0; mi < 4; mi++) {
#pragma unroll
        for (int ni = 0; ni < 4; ni++) {
            int r0 = bm + wm + mi * 16 + (lane >> 2);
            int c0 = bn + wn + ni * 8 + (lane & 3) * 2;
            float bv0 = bias[c0], bv1 = bias[c0 + 1];
            float* p0 = C + (size_t)r0 * GG + c0;
            float* p1 = C + (size_t)(r0 + 8) * GG + c0;
            p0[0] = acc[mi][ni][0] + bv0;
            p0[1] = acc[mi][ni][1] + bv1;
            p1[0] = acc[mi][ni][2] + bv0;
            p1[1] = acc[mi][ni][3] + bv1;
        }
    }
}

// ------------------------------------------------------------------
// 3) GRU recurrence: cluster(8), reg-resident weight frags, 4 acc chains,
//    tanh.approx gates, hardware cluster barrier (R6 sync — R7's mbarrier
//    arrive-storm regressed 2.5x and is reverted).
// ------------------------------------------------------------------
#define CLS 8
#define W_STRIDE 104
#define H_STRIDE 264
#define GT_STRIDE 100
#define OFF_W 0
#define OFF_H (256 * W_STRIDE * 2)
#define OFF_G (OFF_H + 2 * 16 * H_STRIDE * 2)
#define GRU_SMEM2 (OFF_G + 8 * GT_STRIDE * 4)

__device__ __forceinline__ void st_cluster_u64(uint32_t laddr, uint32_t rnk, unsigned long long v) {
    uint32_t ra;
    asm volatile("mapa.shared::cluster.u32 %0, %1, %2;" : "=r"(ra) : "r"(laddr), "r"(rnk));
    asm volatile("st.shared::cluster.u64 [%0], %1;" :: "r"(ra), "l"(v) : "memory");
}
__device__ __forceinline__ void cluster_arrive_() {
    asm volatile("barrier.cluster.arrive.aligned;" ::: "memory");
}
__device__ __forceinline__ void cluster_wait_() {
    asm volatile("barrier.cluster.wait.aligned;" ::: "memory");
}
__device__ __forceinline__ float tanh_fast(float x) {
    float y;
    asm("tanh.approx.f32 %0, %1;" : "=f"(y) : "f"(x));
    return y;
}
__device__ __forceinline__ float sig_fast(float x) {
    return fmaf(0.5f, tanh_fast(0.5f * x), 0.5f);
}

__global__ __launch_bounds__(256) __cluster_dims__(CLS, 1, 1)
void gru_cluster(const float* __restrict__ xw_f, const float* __restrict__ xw_b,
                 const __half* __restrict__ rkh_f, const __half* __restrict__ rkh_b,
                 const float* __restrict__ bin_f, const float* __restrict__ bin_b,
                 __half* __restrict__ out_seq,
                 float* __restrict__ out_final)
{
    extern __shared__ char sm[];
    __half* wsm  = reinterpret_cast<__half*>(sm + OFF_W);
    __half* hbuf = reinterpret_cast<__half*>(sm + OFF_H);
    float*  gt   = reinterpret_cast<float*>(sm + OFF_G);
    uint32_t smb = (uint32_t)__cvta_generic_to_shared(sm);

    int tid = threadIdx.x;
    int lane = tid & 31;
    int wp = tid >> 5;
    uint32_t rank;
    asm("mov.u32 %0, %%cluster_ctarank;" : "=r"(rank));
    int cl  = blockIdx.x / CLS;
    int dir = cl >> 3;
    int bg  = cl & 7;

    const float*  xw  = dir ? xw_b  : xw_f;
    const __half* rkh = dir ? rkh_b : rkh_f;
    const float*  bin = dir ? bin_b : bin_f;

    // init: weights to smem, zero h buffers
    for (int i = tid; i < 256 * 96; i += 256) {
        int k = i / 96, j = i % 96;
        int gcol = (j >> 5) * 256 + (rank << 5) + (j & 31);
        wsm[k * W_STRIDE + j] = rkh[(size_t)k * GG + gcol];
    }
    for (int i = tid; i < 2 * 16 * H_STRIDE; i += 256) hbuf[i] = __half(0.f);

    const int ug = (rank << 5) + lane;
    const float bz = bin[ug];
    const float br = bin[UU + ug];
    const float bh = bin[2 * UU + ug];
    const int gbatch = bg * 8 + wp;

    uint32_t a_off = (uint32_t)((((lane & 7) * H_STRIDE) + ((lane >> 3) & 1) * 8) * 2);
    uint32_t b_addr = smb + OFF_W +
                      (uint32_t)(((lane & 15) * W_STRIDE + 16 * wp + (lane >> 4) * 8) * 2);

    __syncthreads();

    // hoist weight fragments to registers (loop-invariant)
    uint32_t bReg[16][4];
    if (wp < 6) {
#pragma unroll
        for (int kq = 0; kq < 16; kq++)
            ldsm_x4_t(bReg[kq][0], bReg[kq][1], bReg[kq][2], bReg[kq][3],
                      b_addr + kq * 16 * W_STRIDE * 2);
    }

    cluster_arrive_();
    cluster_wait_();   // all CTAs initialized before any remote h writes

    float hn_reg = 0.f;
    float xz, xr, xh;
    {
        int t0 = dir ? (TT - 1) : 0;
        size_t xrow = ((size_t)gbatch * TT + t0) * GG;
        xz = __ldg(&xw[xrow + ug]);
        xr = __ldg(&xw[xrow + UU + ug]);
        xh = __ldg(&xw[xrow + 2 * UU + ug]);
    }

    for (int s = 0; s < TT; s++) {
        int t = dir ? (TT - 1 - s) : s;
        int p = s & 1;

        if (wp < 6) {
            float ac[4][2][4];
#pragma unroll
            for (int c0 = 0; c0 < 4; c0++)
#pragma unroll
                for (int h0 = 0; h0 < 2; h0++)
#pragma unroll
                    for (int e = 0; e < 4; e++) ac[c0][h0][e] = 0.f;
            uint32_t abase = smb + OFF_H + (uint32_t)(p * 16 * H_STRIDE * 2) + a_off;
#pragma unroll
            for (int kq = 0; kq < 16; kq++) {
                uint32_t a[4];
                a[1] = 0u; a[3] = 0u;
                ldsm_x2(a[0], a[2], abase + kq * 32);
                int ch = kq & 3;
                mma16816(ac[ch][0], a, &bReg[kq][0]);
                mma16816(ac[ch][1], a, &bReg[kq][2]);
            }
            int row = lane >> 2;
            int c0  = 16 * wp + (lane & 3) * 2;
#pragma unroll
            for (int h0 = 0; h0 < 2; h0++) {
                float v0 = (ac[0][h0][0] + ac[1][h0][0]) + (ac[2][h0][0] + ac[3][h0][0]);
                float v1 = (ac[0][h0][1] + ac[1][h0][1]) + (ac[2][h0][1] + ac[3][h0][1]);
                *reinterpret_cast<float2*>(&gt[row * GT_STRIDE + c0 + h0 * 8]) = make_float2(v0, v1);
            }
        }

        // prefetch next xw (hidden under mma + barrier)
        float xzn = 0.f, xrn = 0.f, xhn = 0.f;
        if (s + 1 < TT) {
            int tn = dir ? (TT - 2 - s) : (s + 1);
            size_t xrow = ((size_t)gbatch * TT + tn) * GG;
            xzn = __ldg(&xw[xrow + ug]);
            xrn = __ldg(&xw[xrow + UU + ug]);
            xhn = __ldg(&xw[xrow + 2 * UU + ug]);
        }
        __syncthreads();

        // gates: warp = batch, lane = unit
        float rz = gt[wp * GT_STRIDE + lane] + bz;
        float rr = gt[wp * GT_STRIDE + 32 + lane] + br;
        float rh = gt[wp * GT_STRIDE + 64 + lane] + bh;
        float z  = sig_fast(xz + rz);
        float r  = sig_fast(xr + rr);
        float hh = tanh_fast(xh + r * rh);
        float hn = z * hn_reg + (1.f - z) * hh;
        hn_reg = hn;

        // broadcast: writers lane%4==0 pack 4 halves -> u64, store to 8 CTAs
        float v1f = __shfl_down_sync(0xffffffffu, hn, 1);
        float v2f = __shfl_down_sync(0xffffffffu, hn, 2);
        float v3f = __shfl_down_sync(0xffffffffu, hn, 3);
        if ((lane & 3) == 0) {
            __half2 lo = __halves2half2(__float2half_rn(hn),  __float2half_rn(v1f));
            __half2 hi = __halves2half2(__float2half_rn(v2f), __float2half_rn(v3f));
            unsigned long long pk;
            asm("mov.b64 %0, {%1, %2};" : "=l"(pk)
                : "r"(*reinterpret_cast<uint32_t*>(&lo)), "r"(*reinterpret_cast<uint32_t*>(&hi)));
            uint32_t hoff = smb + OFF_H +
                            (uint32_t)((((p ^ 1) * 16 + wp) * H_STRIDE + ug) * 2);
#pragma unroll
            for (uint32_t r2 = 0; r2 < CLS; r2++) st_cluster_u64(hoff, r2, pk);
        }
        cluster_arrive_();   // release: h stores ordered before peers' wait

        if (out_seq)
            out_seq[((size_t)gbatch * TT + t) * (2 * UU) + dir * UU + ug] = __float2half_rn(hn);
        xz = xzn; xr = xrn; xh = xhn;

        cluster_wait_();     // acquire: next step's h reads see all peers' stores
    }

    if (out_final)
        out_final[(size_t)gbatch * (2 * UU) + dir * UU + ug] = hn_reg;
}

// ------------------------------------------------------------------
// 4) output head
// ------------------------------------------------------------------
__global__ void out_kernel(const float* __restrict__ h2,
                           const float* __restrict__ wout,
                           const float* __restrict__ bout,
                           float* __restrict__ out) {
    int b = blockIdx.x;
    int c = threadIdx.x;
    __shared__ float logits[CC];
    if (c < CC) {
        float acc = bout[c];
        const float* hrow = h2 + (size_t)b * (2 * UU);
#pragma unroll 4
        for (int j = 0; j < 2 * UU; j++) acc += hrow[j] * wout[(size_t)j * CC + c];
        logits[c] = acc;
    }
    __syncthreads();
    if (c == 0) {
        float m = logits[0];
#pragma unroll
        for (int i = 1; i < CC; i++) m = fmaxf(m, logits[i]);
        float s = 0.f;
#pragma unroll
        for (int i = 0; i < CC; i++) { float ev = expf(logits[i] - m); logits[i] = ev; s += ev; }
        float inv = 1.f / s;
#pragma unroll
        for (int i = 0; i < CC; i++) out[(size_t)b * CC + i] = logits[i] * inv;
    }
}

// ------------------------------------------------------------------
// Launcher
// ------------------------------------------------------------------
extern "C" void kernel_launch(void* const* d_in, const int* in_sizes, int n_in,
                              void* d_out, int out_size) {
    const int*   x    = (const int*)  d_in[0];
    const float* emb  = (const float*)d_in[1];
    const float* k1f  = (const float*)d_in[2];
    const float* rk1f = (const float*)d_in[3];
    const float* b1f  = (const float*)d_in[4];
    const float* k1b  = (const float*)d_in[5];
    const float* rk1b = (const float*)d_in[6];
    const float* b1b  = (const float*)d_in[7];
    const float* k2f  = (const float*)d_in[8];
    const float* rk2f = (const float*)d_in[9];
    const float* b2f  = (const float*)d_in[10];
    const float* k2b  = (const float*)d_in[11];
    const float* rk2b = (const float*)d_in[12];
    const float* b2b  = (const float*)d_in[13];
    const float* wout = (const float*)d_in[14];
    const float* bout = (const float*)d_in[15];
    float* out = (float*)d_out;

    __half *eh_p, *h1h_p, *rkh1f_p, *rkh1b_p, *rkh2f_p, *rkh2b_p;
    __half *w1hf_p, *w1hb_p, *w2hf_p, *w2hb_p;
    float *xwf_p, *xwb_p, *h2_p;
    cudaGetSymbolAddress((void**)&eh_p,    g_eh);
    cudaGetSymbolAddress((void**)&h1h_p,   g_h1h);
    cudaGetSymbolAddress((void**)&xwf_p,   g_xwf);
    cudaGetSymbolAddress((void**)&xwb_p,   g_xwb);
    cudaGetSymbolAddress((void**)&h2_p,    g_h2);
    cudaGetSymbolAddress((void**)&rkh1f_p, g_rkh1f);
    cudaGetSymbolAddress((void**)&rkh1b_p, g_rkh1b);
    cudaGetSymbolAddress((void**)&rkh2f_p, g_rkh2f);
    cudaGetSymbolAddress((void**)&rkh2b_p, g_rkh2b);
    cudaGetSymbolAddress((void**)&w1hf_p,  g_w1hf);
    cudaGetSymbolAddress((void**)&w1hb_p,  g_w1hb);
    cudaGetSymbolAddress((void**)&w2hf_p,  g_w2hf);
    cudaGetSymbolAddress((void**)&w2hb_p,  g_w2hb);

    cudaFuncSetAttribute(gru_cluster,
                         cudaFuncAttributeMaxDynamicSharedMemorySize, GRU_SMEM2);

    const int M = BB * TT;
    dim3 hgrid(12, M / 128);   // fused fwd+bwd

    convert_all<<<dim3(384, 8), 1024>>>(rk1f, rk1b, rk2f, rk2b, k1f, k1b, k2f, k2b,
                                        rkh1f_p, rkh1b_p, rkh2f_p, rkh2b_p,
                                        w1hf_p, w1hb_p, w2hf_p, w2hb_p);

    gather_h_kernel<<<M, 160>>>(x, emb, eh_p);

    hgemm_dual<<<hgrid, 256>>>(eh_p, w1hf_p, w1hb_p, b1f, b1b, xwf_p, xwb_p, KE, KE);

    gru_cluster<<<128, 256, GRU_SMEM2>>>(xwf_p, xwb_p, rkh1f_p, rkh1b_p,
                                         b1f + GG, b1b + GG, h1h_p, nullptr);

    hgemm_dual<<<hgrid, 256>>>(h1h_p, w2hf_p, w2hb_p, b2f, b2b, xwf_p, xwb_p,
                               2 * UU, 2 * UU);

    gru_cluster<<<128, 256, GRU_SMEM2>>>(xwf_p, xwb_p, rkh2f_p, rkh2b_p,
                                         b2f + GG, b2b + GG, nullptr, h2_p);

    out_kernel<<<BB, 32>>>(h2_p, wout, bout, out);
}

// round 11
// speedup vs baseline: 2.5107x; 1.1912x over previous
#include <cuda_runtime.h>
#include <cuda_fp16.h>
#include <math.h>
#include <stdint.h>

// Problem dims
#define BB 64
#define TT 512
#define EE 300
#define KE 320
#define UU 256
#define GG 768
#define CC 20

// ------------------------------------------------------------------
// Scratch
// ------------------------------------------------------------------
__device__ __half g_eh  [BB * TT * KE];
__device__ __half g_h1h [BB * TT * 2 * UU];
__device__ float  g_xwf [BB * TT * GG];
__device__ float  g_xwb [BB * TT * GG];
__device__ float  g_h2  [BB * 2 * UU];
__device__ __half g_rkh1f[UU * GG];
__device__ __half g_rkh1b[UU * GG];
__device__ __half g_rkh2f[UU * GG];
__device__ __half g_rkh2b[UU * GG];
__device__ __half g_w1hf[KE * GG];
__device__ __half g_w1hb[KE * GG];
__device__ __half g_w2hf[2 * UU * GG];
__device__ __half g_w2hb[2 * UU * GG];

// ------------------------------------------------------------------
// 0) all fp32 -> fp16 conversions, one kernel
// ------------------------------------------------------------------
__global__ void convert_all(const float* __restrict__ rk1f, const float* __restrict__ rk1b,
                            const float* __restrict__ rk2f, const float* __restrict__ rk2b,
                            const float* __restrict__ k1f,  const float* __restrict__ k1b,
                            const float* __restrict__ k2f,  const float* __restrict__ k2b,
                            __half* rkh1f, __half* rkh1b, __half* rkh2f, __half* rkh2b,
                            __half* w1hf,  __half* w1hb,  __half* w2hf,  __half* w2hb) {
    int seg = blockIdx.y;
    int i = blockIdx.x * blockDim.x + threadIdx.x;
    const float* src = nullptr; __half* dst = nullptr; int n = 0; bool pad = false;
    switch (seg) {
        case 0: src = rk1f; dst = rkh1f; n = UU * GG; break;
        case 1: src = rk1b; dst = rkh1b; n = UU * GG; break;
        case 2: src = rk2f; dst = rkh2f; n = UU * GG; break;
        case 3: src = rk2b; dst = rkh2b; n = UU * GG; break;
        case 4: src = k1f;  dst = w1hf;  n = KE * GG; pad = true; break;
        case 5: src = k1b;  dst = w1hb;  n = KE * GG; pad = true; break;
        case 6: src = k2f;  dst = w2hf;  n = 2 * UU * GG; break;
        default: src = k2b; dst = w2hb;  n = 2 * UU * GG; break;
    }
    if (i >= n) return;
    if (pad) {
        int r = i / GG;
        dst[i] = (r < EE) ? __float2half_rn(src[i]) : __half(0.f);
    } else {
        dst[i] = __float2half_rn(src[i]);
    }
}

// ------------------------------------------------------------------
// 1) embedding gather -> fp16, padded to 320
// ------------------------------------------------------------------
__global__ void gather_h_kernel(const int* __restrict__ x,
                                const float* __restrict__ emb,
                                __half* __restrict__ eh) {
    int row = blockIdx.x;
    int t = threadIdx.x;
    const float* src = emb + (size_t)x[row] * EE;
    __half2* dst = reinterpret_cast<__half2*>(eh + (size_t)row * KE);
    if (t < EE / 2) {
        float2 v = *reinterpret_cast<const float2*>(src + 2 * t);
        dst[t] = __floats2half2_rn(v.x, v.y);
    } else if (t < KE / 2) {
        dst[t] = __floats2half2_rn(0.f, 0.f);
    }
}

// ------------------------------------------------------------------
// mma/ldmatrix primitives
// ------------------------------------------------------------------
__device__ __forceinline__ void ldsm_x4(uint32_t& r0, uint32_t& r1, uint32_t& r2, uint32_t& r3,
                                        uint32_t addr) {
    asm volatile("ldmatrix.sync.aligned.m8n8.x4.shared.b16 {%0,%1,%2,%3}, [%4];"
                 : "=r"(r0), "=r"(r1), "=r"(r2), "=r"(r3) : "r"(addr));
}
__device__ __forceinline__ void ldsm_x4_t(uint32_t& r0, uint32_t& r1, uint32_t& r2, uint32_t& r3,
                                          uint32_t addr) {
    asm volatile("ldmatrix.sync.aligned.m8n8.x4.trans.shared.b16 {%0,%1,%2,%3}, [%4];"
                 : "=r"(r0), "=r"(r1), "=r"(r2), "=r"(r3) : "r"(addr));
}
__device__ __forceinline__ void ldsm_x2(uint32_t& r0, uint32_t& r1, uint32_t addr) {
    asm volatile("ldmatrix.sync.aligned.m8n8.x2.shared.b16 {%0,%1}, [%2];"
                 : "=r"(r0), "=r"(r1) : "r"(addr));
}
__device__ __forceinline__ void mma16816(float* c, const uint32_t* a, const uint32_t* b) {
    asm volatile("mma.sync.aligned.m16n8k16.row.col.f32.f16.f16.f32 "
                 "{%0,%1,%2,%3}, {%4,%5,%6,%7}, {%8,%9}, {%0,%1,%2,%3};"
                 : "+f"(c[0]), "+f"(c[1]), "+f"(c[2]), "+f"(c[3])
                 : "r"(a[0]), "r"(a[1]), "r"(a[2]), "r"(a[3]), "r"(b[0]), "r"(b[1]));
}

#define CPA16(s, g) asm volatile("cp.async.cg.shared.global [%0], [%1], 16;" :: "r"(s), "l"(g))
#define CPA_COMMIT() asm volatile("cp.async.commit_group;" ::: "memory")
#define CPA_WAIT2()  asm volatile("cp.async.wait_group 2;" ::: "memory")

// ------------------------------------------------------------------
// 2) Fused dual HGEMM (fwd+bwd), 3-stage cp.async pipeline (kept: R8
//    data shows it beats separate launches by ~70us)
// ------------------------------------------------------------------
#define SA2 40
#define SB 136
#define ASB (128 * SA2 * 2)
#define BSB (32 * SB * 2)

__global__ __launch_bounds__(256)
void hgemm_dual(const __half* __restrict__ A,
                const __half* __restrict__ Bf, const __half* __restrict__ Bb,
                const float* __restrict__ biasf, const float* __restrict__ biasb,
                float* __restrict__ Cf, float* __restrict__ Cb,
                int K, int lda) {
    __shared__ __half As[3][128 * SA2];
    __shared__ __half Bs[3][32 * SB];

    int tid  = threadIdx.x;
    int w    = tid >> 5;
    int lane = tid & 31;
    int half_sel = blockIdx.x / 6;
    const __half* Bw  = half_sel ? Bb : Bf;
    const float* bias = half_sel ? biasb : biasf;
    float* C          = half_sel ? Cb : Cf;
    int bm = blockIdx.y * 128;
    int bn = (blockIdx.x % 6) * 128;
    int wm = (w >> 2) * 64;
    int wn = (w & 3) * 32;

    float acc[4][4][4];
#pragma unroll
    for (int mi = 0; mi < 4; mi++)
#pragma unroll
        for (int ni = 0; ni < 4; ni++)
#pragma unroll
            for (int c = 0; c < 4; c++) acc[mi][ni][c] = 0.f;

    int arow = tid >> 1, acol = (tid & 1) * 16;
    int brow = tid >> 3, bcol = (tid & 7) * 16;
    const __half* Ag = A + (size_t)(bm + arow) * lda + acol;
    const __half* Bg = Bw + (size_t)brow * GG + bn + bcol;

    uint32_t as_st = (uint32_t)__cvta_generic_to_shared(&As[0][arow * SA2 + acol]);
    uint32_t bs_st = (uint32_t)__cvta_generic_to_shared(&Bs[0][brow * SB + bcol]);

    uint32_t a_addr[4], b_addr[2];
#pragma unroll
    for (int mi = 0; mi < 4; mi++) {
        int m  = wm + mi * 16 + (lane & 15);
        int kc = (lane >> 4) * 8;
        a_addr[mi] = (uint32_t)__cvta_generic_to_shared(&As[0][m * SA2 + kc]);
    }
#pragma unroll
    for (int nj = 0; nj < 2; nj++) {
        int kr = lane & 15;
        int nc = wn + nj * 16 + (lane >> 4) * 8;
        b_addr[nj] = (uint32_t)__cvta_generic_to_shared(&Bs[0][kr * SB + nc]);
    }

    int KT = K >> 5;

#pragma unroll
    for (int st = 0; st < 2; st++) {
        const __half* Agp = Ag + st * 32;
        const __half* Bgp = Bg + (size_t)st * 32 * GG;
        CPA16(as_st + st * ASB, Agp);
        CPA16(as_st + st * ASB + 16, Agp + 8);
        CPA16(bs_st + st * BSB, Bgp);
        CPA16(bs_st + st * BSB + 16, Bgp + 8);
        CPA_COMMIT();
    }

    for (int kt = 0; kt < KT; kt++) {
        int cur = kt % 3;
        if (kt + 2 < KT) {
            int nb = (kt + 2) % 3;
            const __half* Agn = Ag + (kt + 2) * 32;
            const __half* Bgn = Bg + (size_t)(kt + 2) * 32 * GG;
            CPA16(as_st + nb * ASB, Agn);
            CPA16(as_st + nb * ASB + 16, Agn + 8);
            CPA16(bs_st + nb * BSB, Bgn);
            CPA16(bs_st + nb * BSB + 16, Bgn + 8);
        }
        CPA_COMMIT();
        CPA_WAIT2();
        __syncthreads();

        uint32_t aoff = cur * ASB;
        uint32_t boff = cur * BSB;
#pragma unroll
        for (int kk = 0; kk < 2; kk++) {
            uint32_t afr[4][4];
            uint32_t bfr[4][2];
#pragma unroll
            for (int mi = 0; mi < 4; mi++)
                ldsm_x4(afr[mi][0], afr[mi][1], afr[mi][2], afr[mi][3],
                        a_addr[mi] + aoff + kk * 16 * 2);
#pragma unroll
            for (int nj = 0; nj < 2; nj++) {
                uint32_t r0, r1, r2, r3;
                ldsm_x4_t(r0, r1, r2, r3, b_addr[nj] + boff + kk * 16 * SB * 2);
                bfr[2 * nj][0] = r0; bfr[2 * nj][1] = r1;
                bfr[2 * nj + 1][0] = r2; bfr[2 * nj + 1][1] = r3;
            }
#pragma unroll
            for (int mi = 0; mi < 4; mi++)
#pragma unroll
                for (int ni = 0; ni < 4; ni++)
                    mma16816(acc[mi][ni], afr[mi], bfr[ni]);
        }
        __syncthreads();
    }

#pragma unroll
    for (int mi = 0; mi < 4; mi++) {
#pragma unroll
        for (int ni = 0; ni < 4; ni++) {
            int r0 = bm + wm + mi * 16 + (lane >> 2);
            int c0 = bn + wn + ni * 8 + (lane & 3) * 2;
            float bv0 = bias[c0], bv1 = bias[c0 + 1];
            float* p0 = C + (size_t)r0 * GG + c0;
            float* p1 = C + (size_t)(r0 + 8) * GG + c0;
            p0[0] = acc[mi][ni][0] + bv0;
            p0[1] = acc[mi][ni][1] + bv1;
            p1[0] = acc[mi][ni][2] + bv0;
            p1[1] = acc[mi][ni][3] + bv1;
        }
    }
}

// ------------------------------------------------------------------
// 3) GRU recurrence: R6 body (flat scalar accumulators — R8's ac[4][2][4]
//    regressed ~220us/launch, likely local-mem demotion), with two
//    independent chains (kq parity, compile-time) and tanh.approx gates.
// ------------------------------------------------------------------
#define CLS 8
#define W_STRIDE 104
#define H_STRIDE 264
#define GT_STRIDE 100
#define OFF_W 0
#define OFF_H (256 * W_STRIDE * 2)
#define OFF_G (OFF_H + 2 * 16 * H_STRIDE * 2)
#define GRU_SMEM2 (OFF_G + 8 * GT_STRIDE * 4)

__device__ __forceinline__ void st_cluster_u64(uint32_t laddr, uint32_t rnk, unsigned long long v) {
    uint32_t ra;
    asm volatile("mapa.shared::cluster.u32 %0, %1, %2;" : "=r"(ra) : "r"(laddr), "r"(rnk));
    asm volatile("st.shared::cluster.u64 [%0], %1;" :: "r"(ra), "l"(v) : "memory");
}
__device__ __forceinline__ void cluster_arrive_() {
    asm volatile("barrier.cluster.arrive.aligned;" ::: "memory");
}
__device__ __forceinline__ void cluster_wait_() {
    asm volatile("barrier.cluster.wait.aligned;" ::: "memory");
}
__device__ __forceinline__ float tanh_fast(float x) {
    float y;
    asm("tanh.approx.f32 %0, %1;" : "=f"(y) : "f"(x));
    return y;
}
__device__ __forceinline__ float sig_fast(float x) {
    return fmaf(0.5f, tanh_fast(0.5f * x), 0.5f);
}

__global__ __launch_bounds__(256) __cluster_dims__(CLS, 1, 1)
void gru_cluster(const float* __restrict__ xw_f, const float* __restrict__ xw_b,
                 const __half* __restrict__ rkh_f, const __half* __restrict__ rkh_b,
                 const float* __restrict__ bin_f, const float* __restrict__ bin_b,
                 __half* __restrict__ out_seq,
                 float* __restrict__ out_final)
{
    extern __shared__ char sm[];
    __half* wsm  = reinterpret_cast<__half*>(sm + OFF_W);
    __half* hbuf = reinterpret_cast<__half*>(sm + OFF_H);
    float*  gt   = reinterpret_cast<float*>(sm + OFF_G);
    uint32_t smb = (uint32_t)__cvta_generic_to_shared(sm);

    int tid = threadIdx.x;
    int lane = tid & 31;
    int wp = tid >> 5;
    uint32_t rank;
    asm("mov.u32 %0, %%cluster_ctarank;" : "=r"(rank));
    int cl  = blockIdx.x / CLS;
    int dir = cl >> 3;
    int bg  = cl & 7;

    const float*  xw  = dir ? xw_b  : xw_f;
    const __half* rkh = dir ? rkh_b : rkh_f;
    const float*  bin = dir ? bin_b : bin_f;

    for (int i = tid; i < 256 * 96; i += 256) {
        int k = i / 96, j = i % 96;
        int gcol = (j >> 5) * 256 + (rank << 5) + (j & 31);
        wsm[k * W_STRIDE + j] = rkh[(size_t)k * GG + gcol];
    }
    for (int i = tid; i < 2 * 16 * H_STRIDE; i += 256) hbuf[i] = __half(0.f);

    const int ug = (rank << 5) + lane;
    const float bz = bin[ug];
    const float br = bin[UU + ug];
    const float bh = bin[2 * UU + ug];
    const int gbatch = bg * 8 + wp;

    uint32_t a_off = (uint32_t)((((lane & 7) * H_STRIDE) + ((lane >> 3) & 1) * 8) * 2);
    uint32_t b_addr = smb + OFF_W +
                      (uint32_t)(((lane & 15) * W_STRIDE + 16 * wp + (lane >> 4) * 8) * 2);

    __syncthreads();

    // hoist weight fragments to registers (loop-invariant)
    uint32_t bReg[16][4];
    if (wp < 6) {
#pragma unroll
        for (int kq = 0; kq < 16; kq++)
            ldsm_x4_t(bReg[kq][0], bReg[kq][1], bReg[kq][2], bReg[kq][3],
                      b_addr + kq * 16 * W_STRIDE * 2);
    }

    cluster_arrive_();
    cluster_wait_();

    float hn_reg = 0.f;
    float xz, xr, xh;
    {
        int t0 = dir ? (TT - 1) : 0;
        size_t xrow = ((size_t)gbatch * TT + t0) * GG;
        xz = __ldg(&xw[xrow + ug]);
        xr = __ldg(&xw[xrow + UU + ug]);
        xh = __ldg(&xw[xrow + 2 * UU + ug]);
    }

    for (int s = 0; s < TT; s++) {
        int t = dir ? (TT - 1 - s) : s;
        int p = s & 1;

        if (wp < 6) {
            // two independent chains per output fragment (kq parity, compile-time)
            float acc0a[4] = {0.f, 0.f, 0.f, 0.f};
            float acc0b[4] = {0.f, 0.f, 0.f, 0.f};
            float acc1a[4] = {0.f, 0.f, 0.f, 0.f};
            float acc1b[4] = {0.f, 0.f, 0.f, 0.f};
            uint32_t abase = smb + OFF_H + (uint32_t)(p * 16 * H_STRIDE * 2) + a_off;
#pragma unroll
            for (int kq = 0; kq < 16; kq++) {
                uint32_t a[4];
                a[1] = 0u; a[3] = 0u;
                ldsm_x2(a[0], a[2], abase + kq * 32);
                if (kq & 1) {
                    mma16816(acc0b, a, &bReg[kq][0]);
                    mma16816(acc1b, a, &bReg[kq][2]);
                } else {
                    mma16816(acc0a, a, &bReg[kq][0]);
                    mma16816(acc1a, a, &bReg[kq][2]);
                }
            }
            int row = lane >> 2;
            int c0  = 16 * wp + (lane & 3) * 2;
            *reinterpret_cast<float2*>(&gt[row * GT_STRIDE + c0]) =
                make_float2(acc0a[0] + acc0b[0], acc0a[1] + acc0b[1]);
            *reinterpret_cast<float2*>(&gt[row * GT_STRIDE + c0 + 8]) =
                make_float2(acc1a[0] + acc1b[0], acc1a[1] + acc1b[1]);
        }

        // prefetch next xw (hidden under mma + barrier)
        float xzn = 0.f, xrn = 0.f, xhn = 0.f;
        if (s + 1 < TT) {
            int tn = dir ? (TT - 2 - s) : (s + 1);
            size_t xrow = ((size_t)gbatch * TT + tn) * GG;
            xzn = __ldg(&xw[xrow + ug]);
            xrn = __ldg(&xw[xrow + UU + ug]);
            xhn = __ldg(&xw[xrow + 2 * UU + ug]);
        }
        __syncthreads();

        // gates: warp = batch, lane = unit
        float rz = gt[wp * GT_STRIDE + lane] + bz;
        float rr = gt[wp * GT_STRIDE + 32 + lane] + br;
        float rh = gt[wp * GT_STRIDE + 64 + lane] + bh;
        float z  = sig_fast(xz + rz);
        float r  = sig_fast(xr + rr);
        float hh = tanh_fast(xh + r * rh);
        float hn = z * hn_reg + (1.f - z) * hh;
        hn_reg = hn;

        // broadcast: writers lane%4==0 pack 4 halves -> u64, store to 8 CTAs
        float v1f = __shfl_down_sync(0xffffffffu, hn, 1);
        float v2f = __shfl_down_sync(0xffffffffu, hn, 2);
        float v3f = __shfl_down_sync(0xffffffffu, hn, 3);
        if ((lane & 3) == 0) {
            __half2 lo = __halves2half2(__float2half_rn(hn),  __float2half_rn(v1f));
            __half2 hi = __halves2half2(__float2half_rn(v2f), __float2half_rn(v3f));
            unsigned long long pk;
            asm("mov.b64 %0, {%1, %2};" : "=l"(pk)
                : "r"(*reinterpret_cast<uint32_t*>(&lo)), "r"(*reinterpret_cast<uint32_t*>(&hi)));
            uint32_t hoff = smb + OFF_H +
                            (uint32_t)((((p ^ 1) * 16 + wp) * H_STRIDE + ug) * 2);
#pragma unroll
            for (uint32_t r2 = 0; r2 < CLS; r2++) st_cluster_u64(hoff, r2, pk);
        }
        cluster_arrive_();   // release: h stores ordered before peers' wait

        if (out_seq)
            out_seq[((size_t)gbatch * TT + t) * (2 * UU) + dir * UU + ug] = __float2half_rn(hn);
        xz = xzn; xr = xrn; xh = xhn;

        cluster_wait_();     // acquire: next step's h reads see peers' stores
    }

    if (out_final)
        out_final[(size_t)gbatch * (2 * UU) + dir * UU + ug] = hn_reg;
}

// ------------------------------------------------------------------
// 4) output head
// ------------------------------------------------------------------
__global__ void out_kernel(const float* __restrict__ h2,
                           const float* __restrict__ wout,
                           const float* __restrict__ bout,
                           float* __restrict__ out) {
    int b = blockIdx.x;
    int c = threadIdx.x;
    __shared__ float logits[CC];
    if (c < CC) {
        float acc = bout[c];
        const float* hrow = h2 + (size_t)b * (2 * UU);
#pragma unroll 4
        for (int j = 0; j < 2 * UU; j++) acc += hrow[j] * wout[(size_t)j * CC + c];
        logits[c] = acc;
    }
    __syncthreads();
    if (c == 0) {
        float m = logits[0];
#pragma unroll
        for (int i = 1; i < CC; i++) m = fmaxf(m, logits[i]);
        float s = 0.f;
#pragma unroll
        for (int i = 0; i < CC; i++) { float ev = expf(logits[i] - m); logits[i] = ev; s += ev; }
        float inv = 1.f / s;
#pragma unroll
        for (int i = 0; i < CC; i++) out[(size_t)b * CC + i] = logits[i] * inv;
    }
}

// ------------------------------------------------------------------
// Launcher
// ------------------------------------------------------------------
extern "C" void kernel_launch(void* const* d_in, const int* in_sizes, int n_in,
                              void* d_out, int out_size) {
    const int*   x    = (const int*)  d_in[0];
    const float* emb  = (const float*)d_in[1];
    const float* k1f  = (const float*)d_in[2];
    const float* rk1f = (const float*)d_in[3];
    const float* b1f  = (const float*)d_in[4];
    const float* k1b  = (const float*)d_in[5];
    const float* rk1b = (const float*)d_in[6];
    const float* b1b  = (const float*)d_in[7];
    const float* k2f  = (const float*)d_in[8];
    const float* rk2f = (const float*)d_in[9];
    const float* b2f  = (const float*)d_in[10];
    const float* k2b  = (const float*)d_in[11];
    const float* rk2b = (const float*)d_in[12];
    const float* b2b  = (const float*)d_in[13];
    const float* wout = (const float*)d_in[14];
    const float* bout = (const float*)d_in[15];
    float* out = (float*)d_out;

    __half *eh_p, *h1h_p, *rkh1f_p, *rkh1b_p, *rkh2f_p, *rkh2b_p;
    __half *w1hf_p, *w1hb_p, *w2hf_p, *w2hb_p;
    float *xwf_p, *xwb_p, *h2_p;
    cudaGetSymbolAddress((void**)&eh_p,    g_eh);
    cudaGetSymbolAddress((void**)&h1h_p,   g_h1h);
    cudaGetSymbolAddress((void**)&xwf_p,   g_xwf);
    cudaGetSymbolAddress((void**)&xwb_p,   g_xwb);
    cudaGetSymbolAddress((void**)&h2_p,    g_h2);
    cudaGetSymbolAddress((void**)&rkh1f_p, g_rkh1f);
    cudaGetSymbolAddress((void**)&rkh1b_p, g_rkh1b);
    cudaGetSymbolAddress((void**)&rkh2f_p, g_rkh2f);
    cudaGetSymbolAddress((void**)&rkh2b_p, g_rkh2b);
    cudaGetSymbolAddress((void**)&w1hf_p,  g_w1hf);
    cudaGetSymbolAddress((void**)&w1hb_p,  g_w1hb);
    cudaGetSymbolAddress((void**)&w2hf_p,  g_w2hf);
    cudaGetSymbolAddress((void**)&w2hb_p,  g_w2hb);

    cudaFuncSetAttribute(gru_cluster,
                         cudaFuncAttributeMaxDynamicSharedMemorySize, GRU_SMEM2);

    const int M = BB * TT;
    dim3 hgrid(12, M / 128);

    convert_all<<<dim3(384, 8), 1024>>>(rk1f, rk1b, rk2f, rk2b, k1f, k1b, k2f, k2b,
                                        rkh1f_p, rkh1b_p, rkh2f_p, rkh2b_p,
                                        w1hf_p, w1hb_p, w2hf_p, w2hb_p);

    gather_h_kernel<<<M, 160>>>(x, emb, eh_p);

    hgemm_dual<<<hgrid, 256>>>(eh_p, w1hf_p, w1hb_p, b1f, b1b, xwf_p, xwb_p, KE, KE);

    gru_cluster<<<128, 256, GRU_SMEM2>>>(xwf_p, xwb_p, rkh1f_p, rkh1b_p,
                                         b1f + GG, b1b + GG, h1h_p, nullptr);

    hgemm_dual<<<hgrid, 256>>>(h1h_p, w2hf_p, w2hb_p, b2f, b2b, xwf_p, xwb_p,
                               2 * UU, 2 * UU);

    gru_cluster<<<128, 256, GRU_SMEM2>>>(xwf_p, xwb_p, rkh2f_p, rkh2b_p,
                                         b2f + GG, b2b + GG, nullptr, h2_p);

    out_kernel<<<BB, 32>>>(h2_p, wout, bout, out);
}